// round 17
// baseline (speedup 1.0000x reference)
#include <cuda_runtime.h>
#include <math.h>

#define SEQ  32768
#define HID  1024
#define RPB  8                  // rows per block (one per warp)
#define NB   (SEQ / RPB)        // 4096 blocks

// Scratch (no device allocation allowed). g_energies/g_bm/g_bs fully
// rewritten each call; g_done self-resets in the finisher block ->
// identical state for every graph replay (deterministic).
__device__ float    g_energies[SEQ];
__device__ float    g_bm[NB];
__device__ float    g_bs[NB];
__device__ unsigned g_done = 0u;

__global__ __launch_bounds__(256) void fused_kernel(
    const float* __restrict__ hidden,
    const float* __restrict__ enc,
    float* __restrict__ out)
{
    __shared__ float4 sh_h[HID / 4];  // 4 KB
    __shared__ float  sh_e[RPB];
    __shared__ bool   sh_last;
    __shared__ float  red[8];

    int tid = threadIdx.x;
    sh_h[tid] = reinterpret_cast<const float4*>(hidden)[tid];
    __syncthreads();

    int warp = tid >> 5;
    int lane = tid & 31;
    int row  = blockIdx.x * RPB + warp;

    const float4* e4 = reinterpret_cast<const float4*>(enc)
                     + (size_t)row * (HID / 4);

    float acc = 0.0f;
#pragma unroll
    for (int i = 0; i < 8; i++) {
        float4 a = __ldcs(e4 + i * 32 + lane);   // streaming: read-once data
        float4 h = sh_h[i * 32 + lane];
        acc = fmaf(a.x, h.x, acc);
        acc = fmaf(a.y, h.y, acc);
        acc = fmaf(a.z, h.z, acc);
        acc = fmaf(a.w, h.w, acc);
    }

#pragma unroll
    for (int o = 16; o; o >>= 1)
        acc += __shfl_xor_sync(0xffffffffu, acc, o);

    if (lane == 0) {
        g_energies[row] = acc;
        sh_e[warp] = acc;
    }
    __syncthreads();

    // lanes 0..7 of warp 0: block LSE pair (m_b, s_b), all float, fixed order
    if (tid < RPB) {
        float e = sh_e[tid];
        float m = e;
#pragma unroll
        for (int o = RPB / 2; o; o >>= 1)
            m = fmaxf(m, __shfl_xor_sync(0xffu, m, o));
        float p = __expf(e - m);
#pragma unroll
        for (int o = RPB / 2; o; o >>= 1)
            p += __shfl_xor_sync(0xffu, p, o);
        if (tid == 0) {
            g_bm[blockIdx.x] = m;
            g_bs[blockIdx.x] = p;
        }
    }

    // -------- last-block-done detection (threadfence reduction pattern) --
    __threadfence();               // publish this block's writes
    if (tid == 0) {
        unsigned t = atomicInc(&g_done, NB - 1);   // wraps to 0 at NB-1
        sh_last = (t == NB - 1);                   // counter now reset
    }
    __syncthreads();
    if (!sh_last) return;          // all but one block retire immediately

    // ==================== EPILOGUE: finisher block only ==================
    // 1) reduce 4096 (m,s) pairs -> global M, S (fixed order, deterministic)
    float m = -INFINITY;
    float bmv[NB / 256];
#pragma unroll
    for (int i = 0; i < NB / 256; i++) {
        bmv[i] = g_bm[i * 256 + tid];
        m = fmaxf(m, bmv[i]);
    }
#pragma unroll
    for (int o = 16; o; o >>= 1)
        m = fmaxf(m, __shfl_xor_sync(0xffffffffu, m, o));
    if (lane == 0) red[warp] = m;
    __syncthreads();
    if (warp == 0) {
        float v = (lane < 8) ? red[lane] : -INFINITY;
#pragma unroll
        for (int o = 4; o; o >>= 1)
            v = fmaxf(v, __shfl_xor_sync(0xffffffffu, v, o));
        if (lane == 0) red[0] = v;
    }
    __syncthreads();
    const float M = red[0];
    __syncthreads();   // red[] reused below

    float s = 0.0f;
#pragma unroll
    for (int i = 0; i < NB / 256; i++)
        s += g_bs[i * 256 + tid] * __expf(bmv[i] - M);
#pragma unroll
    for (int o = 16; o; o >>= 1)
        s += __shfl_xor_sync(0xffffffffu, s, o);
    if (lane == 0) red[warp] = s;
    __syncthreads();
    if (warp == 0) {
        float v = (lane < 8) ? red[lane] : 0.0f;
#pragma unroll
        for (int o = 4; o; o >>= 1)
            v += __shfl_xor_sync(0xffffffffu, v, o);
        if (lane == 0) red[0] = v;
    }
    __syncthreads();
    const float inv = 1.0f / red[0];

    // 2) write all outputs: 256 threads x 32 float4 (energies are L2-hot)
    const float4* e4g = reinterpret_cast<const float4*>(g_energies);
    float4*       o4g = reinterpret_cast<float4*>(out);
#pragma unroll
    for (int i = 0; i < SEQ / 4 / 256; i++) {
        int idx = i * 256 + tid;
        float4 e = e4g[idx];
        float4 r;
        r.x = __expf(e.x - M) * inv;
        r.y = __expf(e.y - M) * inv;
        r.z = __expf(e.z - M) * inv;
        r.w = __expf(e.w - M) * inv;
        o4g[idx] = r;
    }
}

// ---------------------------------------------------------------------------
extern "C" void kernel_launch(void* const* d_in, const int* in_sizes, int n_in,
                              void* d_out, int out_size)
{
    const float* hidden = (const float*)d_in[0];   // [1024]
    const float* enc    = (const float*)d_in[1];   // [32768, 1024]
    float* out          = (float*)d_out;           // [1,1,32768]

    fused_kernel<<<NB, 256>>>(hidden, enc, out);
}